// round 13
// baseline (speedup 1.0000x reference)
#include <cuda_runtime.h>
#include <cuda_bf16.h>
#include <cstdint>

// Problem constants
#define BB 8
#define MM 512
#define HH 512
#define DD 64
#define LL 1024
#define NN 1536   // M + L

// ---------------------------------------------------------------------------
// Scratch (device globals: allocation-free rule)
// ---------------------------------------------------------------------------
__device__ __nv_bfloat16 g_iqh[BB * MM * HH], g_iql[BB * MM * HH];
__device__ __nv_bfloat16 g_ikh[BB * NN * HH], g_ikl[BB * NN * HH];
__device__ __nv_bfloat16 g_ivh[BB * NN * HH], g_ivl[BB * NN * HH];
__device__ __nv_bfloat16 g_hqh[64 * MM * DD], g_hql[64 * MM * DD];
__device__ __nv_bfloat16 g_hkh[64 * NN * DD], g_hkl[64 * NN * DD];
__device__ __nv_bfloat16 g_hvh[64 * NN * DD], g_hvl[64 * NN * DD];
__device__ __nv_bfloat16 g_aoh[BB * MM * HH], g_aol[BB * MM * HH];
__device__ __nv_bfloat16 g_wh[4 * HH * HH], g_wl[4 * HH * HH];
__device__ __nv_bfloat16 g_peh[LL * DD], g_pel[LL * DD];
__device__ float g_sp[64 * MM * LL];

// ---------------------------------------------------------------------------
// PTX helpers
// ---------------------------------------------------------------------------
__device__ __forceinline__ uint32_t smem_u32(const void* p) {
    uint32_t a;
    asm("{ .reg .u64 t; cvta.to.shared.u64 t, %1; cvt.u32.u64 %0, t; }"
        : "=r"(a) : "l"(p));
    return a;
}
#define CPA16(d, s) \
    asm volatile("cp.async.cg.shared.global [%0], [%1], 16;" \
                 :: "r"(d), "l"(s) : "memory")
#define CP_COMMIT() asm volatile("cp.async.commit_group;" ::: "memory")
#define CP_WAIT1() asm volatile("cp.async.wait_group 1;" ::: "memory")
#define CP_WAIT0() asm volatile("cp.async.wait_group 0;" ::: "memory")

__device__ __forceinline__ void ldsm4(uint32_t* r, uint32_t a) {
    asm volatile("ldmatrix.sync.aligned.m8n8.x4.shared.b16 {%0,%1,%2,%3}, [%4];"
                 : "=r"(r[0]), "=r"(r[1]), "=r"(r[2]), "=r"(r[3]) : "r"(a));
}
__device__ __forceinline__ void ldsm4t(uint32_t* r, uint32_t a) {
    asm volatile("ldmatrix.sync.aligned.m8n8.x4.trans.shared.b16 {%0,%1,%2,%3}, [%4];"
                 : "=r"(r[0]), "=r"(r[1]), "=r"(r[2]), "=r"(r[3]) : "r"(a));
}
__device__ __forceinline__ void mma16816(float* c, const uint32_t* a,
                                         const uint32_t* b) {
    asm volatile(
        "mma.sync.aligned.m16n8k16.row.col.f32.bf16.bf16.f32 "
        "{%0,%1,%2,%3}, {%4,%5,%6,%7}, {%8,%9}, {%0,%1,%2,%3};"
        : "+f"(c[0]), "+f"(c[1]), "+f"(c[2]), "+f"(c[3])
        : "r"(a[0]), "r"(a[1]), "r"(a[2]), "r"(a[3]), "r"(b[0]), "r"(b[1]));
}
__device__ __forceinline__ uint32_t packbf(float a, float b) {
    __nv_bfloat162 h = __floats2bfloat162_rn(a, b);
    return *(uint32_t*)&h;
}
__device__ __forceinline__ uint32_t packbf_lo(float a, float b) {
    float ra = a - __bfloat162float(__float2bfloat16(a));
    float rb = b - __bfloat162float(__float2bfloat16(b));
    return packbf(ra, rb);
}

// ---------------------------------------------------------------------------
// Fused split kernel (R10 winner).
// ---------------------------------------------------------------------------
#define Q4 (BB * MM * HH / 4)
#define K4 (BB * NN * HH / 4)
#define W4 (4 * HH * HH / 4)
#define PE4 (DD * LL / 4)
#define TOT4 (Q4 + 2 * K4 + W4 + PE4)

__global__ void __launch_bounds__(256) split_all(
    const float* __restrict__ query, const float* __restrict__ key,
    const float* __restrict__ value,
    const float* __restrict__ w0, const float* __restrict__ w1,
    const float* __restrict__ w2, const float* __restrict__ w3,
    const float* __restrict__ pe,
    __nv_bfloat16* __restrict__ iqh, __nv_bfloat16* __restrict__ iql,
    __nv_bfloat16* __restrict__ ikh, __nv_bfloat16* __restrict__ ikl,
    __nv_bfloat16* __restrict__ ivh, __nv_bfloat16* __restrict__ ivl,
    __nv_bfloat16* __restrict__ wh, __nv_bfloat16* __restrict__ wl,
    __nv_bfloat16* __restrict__ peh, __nv_bfloat16* __restrict__ pel) {
    int i = blockIdx.x * 256 + threadIdx.x;
    if (i >= TOT4) return;

    const float* src;
    __nv_bfloat16 *hi, *lo;
    int j;
    if (i < Q4) {
        src = query; hi = iqh; lo = iql; j = i;
    } else if (i < Q4 + K4) {
        src = key; hi = ikh; lo = ikl; j = i - Q4;
    } else if (i < Q4 + 2 * K4) {
        src = value; hi = ivh; lo = ivl; j = i - Q4 - K4;
    } else if (i < Q4 + 2 * K4 + W4) {
        int jj = i - (Q4 + 2 * K4);
        int widx = jj >> 16;
        j = jj & 65535;
        src = (widx == 0) ? w0 : (widx == 1) ? w1 : (widx == 2) ? w2 : w3;
        hi = wh + (size_t)widx * HH * HH;
        lo = wl + (size_t)widx * HH * HH;
    } else {
        int jj = i - (Q4 + 2 * K4 + W4);
        int base = jj * 4;
#pragma unroll
        for (int e = 0; e < 4; e++) {
            int idx = base + e;
            int d = idx >> 10, l = idx & 1023;
            float v = pe[idx];
            __nv_bfloat16 h = __float2bfloat16(v);
            peh[l * 64 + d] = h;
            pel[l * 64 + d] = __float2bfloat16(v - __bfloat162float(h));
        }
        return;
    }

    float4 v = ((const float4*)src)[j];
    __nv_bfloat16 h0 = __float2bfloat16(v.x), h1 = __float2bfloat16(v.y);
    __nv_bfloat16 h2 = __float2bfloat16(v.z), h3 = __float2bfloat16(v.w);
    ((__nv_bfloat162*)hi)[2 * j]     = __nv_bfloat162(h0, h1);
    ((__nv_bfloat162*)hi)[2 * j + 1] = __nv_bfloat162(h2, h3);
    ((__nv_bfloat162*)lo)[2 * j] = __nv_bfloat162(
        __float2bfloat16(v.x - __bfloat162float(h0)),
        __float2bfloat16(v.y - __bfloat162float(h1)));
    ((__nv_bfloat162*)lo)[2 * j + 1] = __nv_bfloat162(
        __float2bfloat16(v.z - __bfloat162float(h2)),
        __float2bfloat16(v.w - __bfloat162float(h3)));
}

// ---------------------------------------------------------------------------
// FUSED Q/K/V projection (R12 winner).
// ---------------------------------------------------------------------------
#define GSTG 36864
#define GEMM_DYN (3 * GSTG)

__global__ void __launch_bounds__(256) gemm_qkv(
    const __nv_bfloat16* __restrict__ iqh, const __nv_bfloat16* __restrict__ iql,
    const __nv_bfloat16* __restrict__ ikh, const __nv_bfloat16* __restrict__ ikl,
    const __nv_bfloat16* __restrict__ ivh, const __nv_bfloat16* __restrict__ ivl,
    const __nv_bfloat16* __restrict__ wh, const __nv_bfloat16* __restrict__ wl,
    __nv_bfloat16* __restrict__ hqh, __nv_bfloat16* __restrict__ hql,
    __nv_bfloat16* __restrict__ hkh, __nv_bfloat16* __restrict__ hkl,
    __nv_bfloat16* __restrict__ hvh, __nv_bfloat16* __restrict__ hvl) {
    extern __shared__ __align__(128) char dynsm[];
    const int t = threadIdx.x;
    const int wid = t >> 5, lane = t & 31;
    const int wm = wid & 3, wn = wid >> 2;
    const uint32_t sbase = smem_u32(dynsm);

    const int x = blockIdx.x;
    const __nv_bfloat16 *Ah, *Al, *Wh_, *Wl_;
    __nv_bfloat16 *Chi, *Clo;
    int rb, T;
    float scale;
    if (x < 32) {
        Ah = iqh; Al = iql;
        Wh_ = wh; Wl_ = wl;
        Chi = hqh; Clo = hql;
        rb = x * 128; T = MM; scale = 0.125f;
    } else if (x < 128) {
        Ah = ikh; Al = ikl;
        Wh_ = wh + (size_t)HH * HH; Wl_ = wl + (size_t)HH * HH;
        Chi = hkh; Clo = hkl;
        rb = (x - 32) * 128; T = NN; scale = 1.0f;
    } else {
        Ah = ivh; Al = ivl;
        Wh_ = wh + 2 * (size_t)HH * HH; Wl_ = wl + 2 * (size_t)HH * HH;
        Chi = hvh; Clo = hvl;
        rb = (x - 128) * 128; T = NN; scale = 1.0f;
    }
    const int jb = blockIdx.y * 128;

    const uint32_t a_off = (uint32_t)((wm * 32 + (lane & 15)) * 144 + (lane >> 4) * 16);
    const uint32_t b_off = (uint32_t)((wn * 64 + (lane & 7) + ((lane >> 4) & 1) * 8) * 144
                                      + ((lane >> 3) & 1) * 16);

    float acc[2][8][4];
#pragma unroll
    for (int i = 0; i < 2; i++)
#pragma unroll
        for (int j = 0; j < 8; j++)
#pragma unroll
            for (int e = 0; e < 4; e++) acc[i][j][e] = 0.f;

    auto issue_stage = [&](int s, int ch) {
        const int term = ch >> 3, kc = ch & 7;
        const __nv_bfloat16* As = (term == 2) ? Al : Ah;
        const __nv_bfloat16* Ws = (term == 1) ? Wl_ : Wh_;
        const __nv_bfloat16* Ag = As + (size_t)rb * HH + kc * 64;
        const __nv_bfloat16* Wg = Ws + (size_t)jb * HH + kc * 64;
        const uint32_t sA = sbase + s * GSTG;
        const uint32_t sB = sA + 18432;
#pragma unroll
        for (int e = 0; e < 4; e++) {
            int id = t + e * 256, row = id >> 3, seg = id & 7;
            uint32_t dst = row * 144 + seg * 16;
            size_t so = (size_t)row * HH + seg * 8;
            CPA16(sA + dst, Ag + so);
            CPA16(sB + dst, Wg + so);
        }
    };

    issue_stage(0, 0);
    CP_COMMIT();
    issue_stage(1, 1);
    CP_COMMIT();

    for (int ch = 0; ch < 24; ch++) {
        if (ch < 23) CP_WAIT1(); else CP_WAIT0();
        __syncthreads();
        if (ch + 2 < 24) {
            issue_stage((ch + 2) % 3, ch + 2);
            CP_COMMIT();
        }

        const uint32_t sA = sbase + (ch % 3) * GSTG;
        const uint32_t sB = sA + 18432;
#pragma unroll
        for (int ks = 0; ks < 4; ks++) {
            uint32_t a[2][4], b[8][2];
#pragma unroll
            for (int mi = 0; mi < 2; mi++)
                ldsm4(a[mi], sA + a_off + mi * 16 * 144 + ks * 32);
#pragma unroll
            for (int j = 0; j < 4; j++) {
                uint32_t r4[4];
                ldsm4(r4, sB + b_off + j * 16 * 144 + ks * 32);
                b[2 * j][0] = r4[0]; b[2 * j][1] = r4[1];
                b[2 * j + 1][0] = r4[2]; b[2 * j + 1][1] = r4[3];
            }
#pragma unroll
            for (int mi = 0; mi < 2; mi++)
#pragma unroll
                for (int nj = 0; nj < 8; nj++)
                    mma16816(acc[mi][nj], a[mi], b[nj]);
        }
    }

    const int g = lane >> 2, t4 = lane & 3;
#pragma unroll
    for (int mi = 0; mi < 2; mi++) {
        const int r0 = rb + wm * 32 + mi * 16 + g;
#pragma unroll
        for (int nj = 0; nj < 8; nj++) {
            const int jcol = jb + wn * 64 + nj * 8 + t4 * 2;
            float v0 = acc[mi][nj][0] * scale, v1 = acc[mi][nj][1] * scale;
            float v2 = acc[mi][nj][2] * scale, v3 = acc[mi][nj][3] * scale;
            const int head = (jcol >> 6) & 7, dd = jcol & 63;
            int b0 = r0 / T, tt0 = r0 % T;
            int b1 = (r0 + 8) / T, tt1 = (r0 + 8) % T;
            size_t o0 = (((size_t)(b0 * 8 + head) * T + tt0) << 6) + dd;
            size_t o1 = (((size_t)(b1 * 8 + head) * T + tt1) << 6) + dd;
            *(uint32_t*)(Chi + o0) = packbf(v0, v1);
            *(uint32_t*)(Chi + o1) = packbf(v2, v3);
            *(uint32_t*)(Clo + o0) = packbf_lo(v0, v1);
            *(uint32_t*)(Clo + o1) = packbf_lo(v2, v3);
        }
    }
}

// ---------------------------------------------------------------------------
// Output projection GEMM (fp32 out).
// ---------------------------------------------------------------------------
__global__ void __launch_bounds__(256) gemm_out(const __nv_bfloat16* __restrict__ Ah,
                                                const __nv_bfloat16* __restrict__ Al,
                                                const __nv_bfloat16* __restrict__ Wh,
                                                const __nv_bfloat16* __restrict__ Wl,
                                                float* __restrict__ C) {
    extern __shared__ __align__(128) char dynsm[];
    const int t = threadIdx.x;
    const int wid = t >> 5, lane = t & 31;
    const int wm = wid & 3, wn = wid >> 2;
    const int rb = blockIdx.x * 128, jb = blockIdx.y * 128;
    const uint32_t sbase = smem_u32(dynsm);

    const uint32_t a_off = (uint32_t)((wm * 32 + (lane & 15)) * 144 + (lane >> 4) * 16);
    const uint32_t b_off = (uint32_t)((wn * 64 + (lane & 7) + ((lane >> 4) & 1) * 8) * 144
                                      + ((lane >> 3) & 1) * 16);

    float acc[2][8][4];
#pragma unroll
    for (int i = 0; i < 2; i++)
#pragma unroll
        for (int j = 0; j < 8; j++)
#pragma unroll
            for (int e = 0; e < 4; e++) acc[i][j][e] = 0.f;

    auto issue_stage = [&](int s, int ch) {
        const int term = ch >> 3, kc = ch & 7;
        const __nv_bfloat16* As = (term == 2) ? Al : Ah;
        const __nv_bfloat16* Ws = (term == 1) ? Wl : Wh;
        const __nv_bfloat16* Ag = As + (size_t)rb * HH + kc * 64;
        const __nv_bfloat16* Wg = Ws + (size_t)jb * HH + kc * 64;
        const uint32_t sA = sbase + s * GSTG;
        const uint32_t sB = sA + 18432;
#pragma unroll
        for (int e = 0; e < 4; e++) {
            int id = t + e * 256, row = id >> 3, seg = id & 7;
            uint32_t dst = row * 144 + seg * 16;
            size_t so = (size_t)row * HH + seg * 8;
            CPA16(sA + dst, Ag + so);
            CPA16(sB + dst, Wg + so);
        }
    };

    issue_stage(0, 0);
    CP_COMMIT();
    issue_stage(1, 1);
    CP_COMMIT();

    for (int ch = 0; ch < 24; ch++) {
        if (ch < 23) CP_WAIT1(); else CP_WAIT0();
        __syncthreads();
        if (ch + 2 < 24) {
            issue_stage((ch + 2) % 3, ch + 2);
            CP_COMMIT();
        }

        const uint32_t sA = sbase + (ch % 3) * GSTG;
        const uint32_t sB = sA + 18432;
#pragma unroll
        for (int ks = 0; ks < 4; ks++) {
            uint32_t a[2][4], b[8][2];
#pragma unroll
            for (int mi = 0; mi < 2; mi++)
                ldsm4(a[mi], sA + a_off + mi * 16 * 144 + ks * 32);
#pragma unroll
            for (int j = 0; j < 4; j++) {
                uint32_t r4[4];
                ldsm4(r4, sB + b_off + j * 16 * 144 + ks * 32);
                b[2 * j][0] = r4[0]; b[2 * j][1] = r4[1];
                b[2 * j + 1][0] = r4[2]; b[2 * j + 1][1] = r4[3];
            }
#pragma unroll
            for (int mi = 0; mi < 2; mi++)
#pragma unroll
                for (int nj = 0; nj < 8; nj++)
                    mma16816(acc[mi][nj], a[mi], b[nj]);
        }
    }

    const int g = lane >> 2, t4 = lane & 3;
#pragma unroll
    for (int mi = 0; mi < 2; mi++) {
        const int r0 = rb + wm * 32 + mi * 16 + g;
#pragma unroll
        for (int nj = 0; nj < 8; nj++) {
            const int jcol = jb + wn * 64 + nj * 8 + t4 * 2;
            *(float2*)(C + (size_t)r0 * HH + jcol) =
                make_float2(acc[mi][nj][0], acc[mi][nj][1]);
            *(float2*)(C + (size_t)(r0 + 8) * HH + jcol) =
                make_float2(acc[mi][nj][2], acc[mi][nj][3]);
        }
    }
}

// ---------------------------------------------------------------------------
// Spos GEMM, single-shot (R9 winner).
// ---------------------------------------------------------------------------
#define SP_SMEM (4 * 18432)

__global__ void __launch_bounds__(256) gemm_sp(const __nv_bfloat16* __restrict__ qhh,
                                               const __nv_bfloat16* __restrict__ qhl,
                                               const __nv_bfloat16* __restrict__ peh,
                                               const __nv_bfloat16* __restrict__ pel,
                                               float* __restrict__ spout) {
    extern __shared__ __align__(16) char spsm[];
    const int t = threadIdx.x;
    const int wid = t >> 5, lane = t & 31;
    const int wm = wid & 3, wn = wid >> 2;
    const int mb = blockIdx.x, lb = blockIdx.y, bh = blockIdx.z;
    const uint32_t sbase = smem_u32(spsm);

    float acc[2][8][4];
#pragma unroll
    for (int i = 0; i < 2; i++)
#pragma unroll
        for (int j = 0; j < 8; j++)
#pragma unroll
            for (int e = 0; e < 4; e++) acc[i][j][e] = 0.f;

    {
        const __nv_bfloat16* aH = qhh + ((size_t)bh * MM + mb * 128) * 64;
        const __nv_bfloat16* aL = qhl + ((size_t)bh * MM + mb * 128) * 64;
        const __nv_bfloat16* bH = peh + (size_t)(lb * 128) * 64;
        const __nv_bfloat16* bL = pel + (size_t)(lb * 128) * 64;
#pragma unroll
        for (int e = 0; e < 4; e++) {
            int id = t + e * 256, row = id >> 3, seg = id & 7;
            uint32_t dst = row * 144 + seg * 16;
            size_t so = (size_t)row * 64 + seg * 8;
            *(uint4*)(spsm + dst) = *(const uint4*)(aH + so);
            *(uint4*)(spsm + 18432 + dst) = *(const uint4*)(aL + so);
            *(uint4*)(spsm + 36864 + dst) = *(const uint4*)(bH + so);
            *(uint4*)(spsm + 55296 + dst) = *(const uint4*)(bL + so);
        }
    }
    __syncthreads();

    const uint32_t aoff_rel = (wm * 32 + (lane & 15)) * 144 + (lane >> 4) * 16;
    const uint32_t boff_rel = (wn * 64 + (lane & 7) + ((lane >> 4) & 1) * 8) * 144
                            + ((lane >> 3) & 1) * 16;
    auto domma = [&](uint32_t aB, uint32_t bB) {
#pragma unroll
        for (int ks = 0; ks < 4; ks++) {
            uint32_t a0[4], a1[4];
            ldsm4(a0, aB + aoff_rel + ks * 32);
            ldsm4(a1, aB + aoff_rel + 16 * 144 + ks * 32);
#pragma unroll
            for (int nb = 0; nb < 4; nb++) {
                uint32_t r4[4];
                ldsm4(r4, bB + boff_rel + nb * 16 * 144 + ks * 32);
                mma16816(acc[0][2 * nb], a0, r4);
                mma16816(acc[0][2 * nb + 1], a0, r4 + 2);
                mma16816(acc[1][2 * nb], a1, r4);
                mma16816(acc[1][2 * nb + 1], a1, r4 + 2);
            }
        }
    };
    domma(sbase,         sbase + 36864);
    domma(sbase + 18432, sbase + 36864);
    domma(sbase,         sbase + 55296);

    const int g = lane >> 2, t4 = lane & 3;
#pragma unroll
    for (int mi = 0; mi < 2; mi++) {
        int m = mb * 128 + wm * 32 + mi * 16 + g;
#pragma unroll
        for (int nj = 0; nj < 8; nj++) {
            int l = lb * 128 + wn * 64 + nj * 8 + t4 * 2;
            float* d0 = spout + ((size_t)bh * MM + m) * 1024 + l;
            *(float2*)d0 = make_float2(acc[mi][nj][0], acc[mi][nj][1]);
            *(float2*)(d0 + 8 * 1024) = make_float2(acc[mi][nj][2], acc[mi][nj][3]);
        }
    }
}

// ---------------------------------------------------------------------------
// HMMA flash banded attention — smem reduced to 69,632B (Q overlays K/V
// region in the prologue) to allow 3 CTAs/SM (12 warps, occ 11.6% -> ~17%).
// ---------------------------------------------------------------------------
#define SKH 0
#define SKL 9216
#define SVH 18432
#define SVL 27648
#define SSP 36864
#define ATTN_SMEM (SSP + 64 * 128 * 4)   // 69632

__global__ void __launch_bounds__(128) attn3(
    const __nv_bfloat16* __restrict__ qhh, const __nv_bfloat16* __restrict__ qhl,
    const __nv_bfloat16* __restrict__ khh, const __nv_bfloat16* __restrict__ khl,
    const __nv_bfloat16* __restrict__ vhh, const __nv_bfloat16* __restrict__ vhl,
    const float* __restrict__ sp,
    __nv_bfloat16* __restrict__ aoh, __nv_bfloat16* __restrict__ aol) {
    extern __shared__ __align__(16) char smc[];
    const uint32_t sb = smem_u32(smc);
    float* sSpf = (float*)(smc + SSP);

    const int m0 = blockIdx.x * 64;
    const int bh = blockIdx.y;
    const int t = threadIdx.x, lane = t & 31, wm = t >> 5;
    const int g = lane >> 2, t4 = lane & 3;
    const int i0 = wm * 16 + g;

    // ---- stage Q into the K/V region (prologue only), extract, release ----
#pragma unroll
    for (int e = 0; e < 4; e++) {
        int id = t + e * 128, row = id >> 3, seg = id & 7;
        size_t srow = ((size_t)bh * MM + m0 + row) * 64 + seg * 8;
        uint32_t dst = row * 144 + seg * 16;
        *(uint4*)(smc + SKH + dst) = *(const uint4*)(qhh + srow);
        *(uint4*)(smc + SKL + dst) = *(const uint4*)(qhl + srow);
    }
    __syncthreads();

    uint32_t qa_h[4][4], qa_l[4][4];
    {
        const uint32_t arel = (wm * 16 + (lane & 15)) * 144 + (lane >> 4) * 16;
#pragma unroll
        for (int ks = 0; ks < 4; ks++) {
            ldsm4(qa_h[ks], sb + SKH + arel + ks * 32);
            ldsm4(qa_l[ks], sb + SKL + arel + ks * 32);
        }
    }
    // (chunk-loop's leading __syncthreads() orders Q extraction before the
    //  first K staging overwrites this region)

    const uint32_t bKrel = ((lane & 7) + ((lane >> 4) & 1) * 8) * 144
                         + ((lane >> 3) & 1) * 16;
    const uint32_t bVrel = (lane & 15) * 144 + (lane >> 4) * 16;

    float o[8][4];
#pragma unroll
    for (int j = 0; j < 8; j++)
#pragma unroll
        for (int e = 0; e < 4; e++) o[j][e] = 0.f;
    float rmax0 = -1e30f, rmax1 = -1e30f, rsum0 = 0.f, rsum1 = 0.f;

    for (int c = 0; c < 17; c++) {
        __syncthreads();
        // ---- stage K, V hi/lo ----
        {
            const size_t nbase = (size_t)bh * NN + m0 + c * 64;
#pragma unroll
            for (int e = 0; e < 4; e++) {
                int id = t + e * 128, row = id >> 3, seg = id & 7;
                size_t srow = (nbase + row) * 64 + seg * 8;
                uint32_t dst = row * 144 + seg * 16;
                *(uint4*)(smc + SKH + dst) = *(const uint4*)(khh + srow);
                *(uint4*)(smc + SKL + dst) = *(const uint4*)(khl + srow);
                *(uint4*)(smc + SVH + dst) = *(const uint4*)(vhh + srow);
                *(uint4*)(smc + SVL + dst) = *(const uint4*)(vhl + srow);
            }
        }
        // ---- stage Spos RING: only the 64 new cols [64c, 64c+64) ----
        {
            const int destbase = 64 * (c & 1);
            const int gbase = c * 64;
#pragma unroll
            for (int e = 0; e < 8; e++) {
                int id = t + e * 128;
                int row = id >> 4, q4 = id & 15;
                int gcol = gbase + q4 * 4;
                float4 v;
                if (gcol < 1024)
                    v = *(const float4*)(sp + ((size_t)bh * MM + m0 + row) * 1024 + gcol);
                else
                    v = make_float4(0.f, 0.f, 0.f, 0.f);
                *(float4*)&sSpf[row * 128 + destbase + q4 * 4] = v;
            }
        }
        __syncthreads();

        // ---- S = qhat . k (3-term) ----
        float s[8][4];
#pragma unroll
        for (int j = 0; j < 8; j++)
#pragma unroll
            for (int e = 0; e < 4; e++) s[j][e] = 0.f;
#pragma unroll
        for (int ks = 0; ks < 4; ks++) {
#pragma unroll
            for (int nb = 0; nb < 4; nb++) {
                uint32_t rh[4], rl[4];
                ldsm4(rh, sb + SKH + bKrel + nb * 16 * 144 + ks * 32);
                ldsm4(rl, sb + SKL + bKrel + nb * 16 * 144 + ks * 32);
                mma16816(s[2 * nb],     qa_h[ks], rh);
                mma16816(s[2 * nb + 1], qa_h[ks], rh + 2);
                mma16816(s[2 * nb],     qa_l[ks], rh);
                mma16816(s[2 * nb + 1], qa_l[ks], rh + 2);
                mma16816(s[2 * nb],     qa_h[ks], rl);
                mma16816(s[2 * nb + 1], qa_h[ks], rl + 2);
            }
        }

        // ---- add Spos via ring index; stale entries masked below ----
#pragma unroll
        for (int nj = 0; nj < 8; nj++) {
            int base = 64 * c + nj * 8 + t4 * 2 - i0 + 128;
            s[nj][0] += sSpf[i0 * 128 + (base & 127)];
            s[nj][1] += sSpf[i0 * 128 + ((base + 1) & 127)];
            s[nj][2] += sSpf[(i0 + 8) * 128 + ((base - 8) & 127)];
            s[nj][3] += sSpf[(i0 + 8) * 128 + ((base - 7) & 127)];
        }
        if (c == 0) {
#pragma unroll
            for (int nj = 0; nj < 8; nj++) {
                int j0 = nj * 8 + t4 * 2;
                if (j0 < i0) s[nj][0] = -1e30f;
                if (j0 + 1 < i0) s[nj][1] = -1e30f;
                if (j0 < i0 + 8) s[nj][2] = -1e30f;
                if (j0 + 1 < i0 + 8) s[nj][3] = -1e30f;
            }
        } else if (c == 16) {
#pragma unroll
            for (int nj = 0; nj < 8; nj++) {
                int j0 = nj * 8 + t4 * 2;
                if (j0 >= i0) s[nj][0] = -1e30f;
                if (j0 + 1 >= i0) s[nj][1] = -1e30f;
                if (j0 >= i0 + 8) s[nj][2] = -1e30f;
                if (j0 + 1 >= i0 + 8) s[nj][3] = -1e30f;
            }
        }

        // ---- online softmax ----
        {
            float mx0 = -1e30f, mx1 = -1e30f;
#pragma unroll
            for (int nj = 0; nj < 8; nj++) {
                mx0 = fmaxf(mx0, fmaxf(s[nj][0], s[nj][1]));
                mx1 = fmaxf(mx1, fmaxf(s[nj][2], s[nj][3]));
            }
            mx0 = fmaxf(mx0, __shfl_xor_sync(0xffffffffu, mx0, 1));
            mx0 = fmaxf(mx0, __shfl_xor_sync(0xffffffffu, mx0, 2));
            mx1 = fmaxf(mx1, __shfl_xor_sync(0xffffffffu, mx1, 1));
            mx1 = fmaxf(mx1, __shfl_xor_sync(0xffffffffu, mx1, 2));
            float nm0 = fmaxf(rmax0, mx0), nm1 = fmaxf(rmax1, mx1);
            float corr0 = __expf(rmax0 - nm0), corr1 = __expf(rmax1 - nm1);
            rmax0 = nm0; rmax1 = nm1;
            float ls0 = 0.f, ls1 = 0.f;
#pragma unroll
            for (int nj = 0; nj < 8; nj++) {
                s[nj][0] = __expf(s[nj][0] - nm0);
                s[nj][1] = __expf(s[nj][1] - nm0);
                s[nj][2] = __expf(s[nj][2] - nm1);
                s[nj][3] = __expf(s[nj][3] - nm1);
                ls0 += s[nj][0] + s[nj][1];
                ls1 += s[nj][2] + s[nj][3];
            }
            ls0 += __shfl_xor_sync(0xffffffffu, ls0, 1);
            ls0 += __shfl_xor_sync(0xffffffffu, ls0, 2);
            ls1 += __shfl_xor_sync(0xffffffffu, ls1, 1);
            ls1 += __shfl_xor_sync(0xffffffffu, ls1, 2);
            rsum0 = rsum0 * corr0 + ls0;
            rsum1 = rsum1 * corr1 + ls1;
#pragma unroll
            for (int j = 0; j < 8; j++) {
                o[j][0] *= corr0; o[j][1] *= corr0;
                o[j][2] *= corr1; o[j][3] *= corr1;
            }
        }

        // ---- O += P . V (3-term, P split in registers) ----
#pragma unroll
        for (int ks = 0; ks < 4; ks++) {
            uint32_t pah[4], pal[4];
            pah[0] = packbf(s[2 * ks][0], s[2 * ks][1]);
            pah[1] = packbf(s[2 * ks][2], s[2 * ks][3]);
            pah[2] = packbf(s[2 * ks + 1][0], s[2 * ks + 1][1]);
            pah[3] = packbf(s[2 * ks + 1][2], s[2 * ks + 1][3]);
            pal[0] = packbf_lo(s[2 * ks][0], s[2 * ks][1]);
            pal[1] = packbf_lo(s[2 * ks][2], s[2 * ks][3]);
            pal[2] = packbf_lo(s[2 * ks + 1][0], s[2 * ks + 1][1]);
            pal[3] = packbf_lo(s[2 * ks + 1][2], s[2 * ks + 1][3]);
#pragma unroll
            for (int dj = 0; dj < 4; dj++) {
                uint32_t rh[4], rl[4];
                ldsm4t(rh, sb + SVH + bVrel + ks * 16 * 144 + dj * 32);
                ldsm4t(rl, sb + SVL + bVrel + ks * 16 * 144 + dj * 32);
                mma16816(o[2 * dj],     pah, rh);
                mma16816(o[2 * dj + 1], pah, rh + 2);
                mma16816(o[2 * dj],     pal, rh);
                mma16816(o[2 * dj + 1], pal, rh + 2);
                mma16816(o[2 * dj],     pah, rl);
                mma16816(o[2 * dj + 1], pah, rl + 2);
            }
        }
    }

    // ---- epilogue ----
    {
        float inv0 = 1.f / rsum0, inv1 = 1.f / rsum1;
        int b = bh >> 3, hd = bh & 7;
        int mr = m0 + i0;
#pragma unroll
        for (int nj = 0; nj < 8; nj++) {
            int col = hd * 64 + nj * 8 + t4 * 2;
            size_t idx0 = ((size_t)(b * MM + mr) * HH) + col;
            size_t idx1 = ((size_t)(b * MM + mr + 8) * HH) + col;
            float a0 = o[nj][0] * inv0, a1 = o[nj][1] * inv0;
            float a2 = o[nj][2] * inv1, a3 = o[nj][3] * inv1;
            *(uint32_t*)(aoh + idx0) = packbf(a0, a1);
            *(uint32_t*)(aoh + idx1) = packbf(a2, a3);
            *(uint32_t*)(aol + idx0) = packbf_lo(a0, a1);
            *(uint32_t*)(aol + idx1) = packbf_lo(a2, a3);
        }
    }
}

// ---------------------------------------------------------------------------
extern "C" void kernel_launch(void* const* d_in, const int* in_sizes, int n_in,
                              void* d_out, int out_size) {
    const float* query  = (const float*)d_in[0];
    const float* key    = (const float*)d_in[1];
    const float* value  = (const float*)d_in[2];
    const float* key_pe = (const float*)d_in[3];
    const float* Wq     = (const float*)d_in[4];
    const float* Wk     = (const float*)d_in[5];
    const float* Wv     = (const float*)d_in[6];
    const float* Wo     = (const float*)d_in[7];
    float* out = (float*)d_out;

    __nv_bfloat16 *iqh, *iql, *ikh, *ikl, *ivh, *ivl;
    __nv_bfloat16 *hqh, *hql, *hkh, *hkl, *hvh, *hvl;
    __nv_bfloat16 *aoh, *aol, *wh, *wl, *peh, *pel;
    float* spb;
    cudaGetSymbolAddress((void**)&iqh, g_iqh); cudaGetSymbolAddress((void**)&iql, g_iql);
    cudaGetSymbolAddress((void**)&ikh, g_ikh); cudaGetSymbolAddress((void**)&ikl, g_ikl);
    cudaGetSymbolAddress((void**)&ivh, g_ivh); cudaGetSymbolAddress((void**)&ivl, g_ivl);
    cudaGetSymbolAddress((void**)&hqh, g_hqh); cudaGetSymbolAddress((void**)&hql, g_hql);
    cudaGetSymbolAddress((void**)&hkh, g_hkh); cudaGetSymbolAddress((void**)&hkl, g_hkl);
    cudaGetSymbolAddress((void**)&hvh, g_hvh); cudaGetSymbolAddress((void**)&hvl, g_hvl);
    cudaGetSymbolAddress((void**)&aoh, g_aoh); cudaGetSymbolAddress((void**)&aol, g_aol);
    cudaGetSymbolAddress((void**)&wh, g_wh);   cudaGetSymbolAddress((void**)&wl, g_wl);
    cudaGetSymbolAddress((void**)&peh, g_peh); cudaGetSymbolAddress((void**)&pel, g_pel);
    cudaGetSymbolAddress((void**)&spb, g_sp);

    static bool attr_set = false;
    if (!attr_set) {
        cudaFuncSetAttribute(attn3, cudaFuncAttributeMaxDynamicSharedMemorySize,
                             ATTN_SMEM);
        cudaFuncSetAttribute(gemm_sp, cudaFuncAttributeMaxDynamicSharedMemorySize,
                             SP_SMEM);
        cudaFuncSetAttribute(gemm_qkv, cudaFuncAttributeMaxDynamicSharedMemorySize,
                             GEMM_DYN);
        cudaFuncSetAttribute(gemm_out, cudaFuncAttributeMaxDynamicSharedMemorySize,
                             GEMM_DYN);
        attr_set = true;
    }

    // fused splits (one launch)
    split_all<<<(TOT4 + 255) / 256, 256>>>(query, key, value, Wq, Wk, Wv, Wo,
                                           key_pe, iqh, iql, ikh, ikl, ivh, ivl,
                                           wh, wl, peh, pel);

    // FUSED Q+K+V projections
    gemm_qkv<<<dim3(224, 4), 256, GEMM_DYN>>>(iqh, iql, ikh, ikl, ivh, ivl,
                                              wh, wl, hqh, hql, hkh, hkl,
                                              hvh, hvl);

    // positional score table
    gemm_sp<<<dim3(MM / 128, LL / 128, 64), 256, SP_SMEM>>>(hqh, hql, peh, pel, spb);

    // flash banded attention
    attn3<<<dim3(MM / 64, 64), 128, ATTN_SMEM>>>(hqh, hql, hkh, hkl, hvh, hvl,
                                                 spb, aoh, aol);

    // output projection (fp32 out)
    gemm_out<<<dim3(BB * MM / 128, 4), 256, GEMM_DYN>>>(
        aoh, aol, wh + 3 * (size_t)HH * HH, wl + 3 * (size_t)HH * HH, out);
}

// round 14
// speedup vs baseline: 1.0520x; 1.0520x over previous
#include <cuda_runtime.h>
#include <cuda_bf16.h>
#include <cstdint>

// Problem constants
#define BB 8
#define MM 512
#define HH 512
#define DD 64
#define LL 1024
#define NN 1536   // M + L

// ---------------------------------------------------------------------------
// Scratch (device globals: allocation-free rule)
// ---------------------------------------------------------------------------
__device__ __nv_bfloat16 g_iqh[BB * MM * HH], g_iql[BB * MM * HH];
__device__ __nv_bfloat16 g_ikh[BB * NN * HH], g_ikl[BB * NN * HH];
__device__ __nv_bfloat16 g_ivh[BB * NN * HH], g_ivl[BB * NN * HH];
__device__ __nv_bfloat16 g_hqh[64 * MM * DD], g_hql[64 * MM * DD];
__device__ __nv_bfloat16 g_hkh[64 * NN * DD], g_hkl[64 * NN * DD];
__device__ __nv_bfloat16 g_hvh[64 * NN * DD], g_hvl[64 * NN * DD];
__device__ __nv_bfloat16 g_aoh[BB * MM * HH], g_aol[BB * MM * HH];
__device__ __nv_bfloat16 g_wh[4 * HH * HH], g_wl[4 * HH * HH];
__device__ __nv_bfloat16 g_peh[LL * DD], g_pel[LL * DD];

// ---------------------------------------------------------------------------
// PTX helpers
// ---------------------------------------------------------------------------
__device__ __forceinline__ uint32_t smem_u32(const void* p) {
    uint32_t a;
    asm("{ .reg .u64 t; cvta.to.shared.u64 t, %1; cvt.u32.u64 %0, t; }"
        : "=r"(a) : "l"(p));
    return a;
}
#define CPA16(d, s) \
    asm volatile("cp.async.cg.shared.global [%0], [%1], 16;" \
                 :: "r"(d), "l"(s) : "memory")
#define CP_COMMIT() asm volatile("cp.async.commit_group;" ::: "memory")
#define CP_WAIT1() asm volatile("cp.async.wait_group 1;" ::: "memory")
#define CP_WAIT0() asm volatile("cp.async.wait_group 0;" ::: "memory")

__device__ __forceinline__ void ldsm4(uint32_t* r, uint32_t a) {
    asm volatile("ldmatrix.sync.aligned.m8n8.x4.shared.b16 {%0,%1,%2,%3}, [%4];"
                 : "=r"(r[0]), "=r"(r[1]), "=r"(r[2]), "=r"(r[3]) : "r"(a));
}
__device__ __forceinline__ void ldsm4t(uint32_t* r, uint32_t a) {
    asm volatile("ldmatrix.sync.aligned.m8n8.x4.trans.shared.b16 {%0,%1,%2,%3}, [%4];"
                 : "=r"(r[0]), "=r"(r[1]), "=r"(r[2]), "=r"(r[3]) : "r"(a));
}
__device__ __forceinline__ void mma16816(float* c, const uint32_t* a,
                                         const uint32_t* b) {
    asm volatile(
        "mma.sync.aligned.m16n8k16.row.col.f32.bf16.bf16.f32 "
        "{%0,%1,%2,%3}, {%4,%5,%6,%7}, {%8,%9}, {%0,%1,%2,%3};"
        : "+f"(c[0]), "+f"(c[1]), "+f"(c[2]), "+f"(c[3])
        : "r"(a[0]), "r"(a[1]), "r"(a[2]), "r"(a[3]), "r"(b[0]), "r"(b[1]));
}
__device__ __forceinline__ uint32_t packbf(float a, float b) {
    __nv_bfloat162 h = __floats2bfloat162_rn(a, b);
    return *(uint32_t*)&h;
}
__device__ __forceinline__ uint32_t packbf_lo(float a, float b) {
    float ra = a - __bfloat162float(__float2bfloat16(a));
    float rb = b - __bfloat162float(__float2bfloat16(b));
    return packbf(ra, rb);
}

// ---------------------------------------------------------------------------
// Fused split kernel (R10 winner).
// ---------------------------------------------------------------------------
#define Q4 (BB * MM * HH / 4)
#define K4 (BB * NN * HH / 4)
#define W4 (4 * HH * HH / 4)
#define PE4 (DD * LL / 4)
#define TOT4 (Q4 + 2 * K4 + W4 + PE4)

__global__ void __launch_bounds__(256) split_all(
    const float* __restrict__ query, const float* __restrict__ key,
    const float* __restrict__ value,
    const float* __restrict__ w0, const float* __restrict__ w1,
    const float* __restrict__ w2, const float* __restrict__ w3,
    const float* __restrict__ pe,
    __nv_bfloat16* __restrict__ iqh, __nv_bfloat16* __restrict__ iql,
    __nv_bfloat16* __restrict__ ikh, __nv_bfloat16* __restrict__ ikl,
    __nv_bfloat16* __restrict__ ivh, __nv_bfloat16* __restrict__ ivl,
    __nv_bfloat16* __restrict__ wh, __nv_bfloat16* __restrict__ wl,
    __nv_bfloat16* __restrict__ peh, __nv_bfloat16* __restrict__ pel) {
    int i = blockIdx.x * 256 + threadIdx.x;
    if (i >= TOT4) return;

    const float* src;
    __nv_bfloat16 *hi, *lo;
    int j;
    if (i < Q4) {
        src = query; hi = iqh; lo = iql; j = i;
    } else if (i < Q4 + K4) {
        src = key; hi = ikh; lo = ikl; j = i - Q4;
    } else if (i < Q4 + 2 * K4) {
        src = value; hi = ivh; lo = ivl; j = i - Q4 - K4;
    } else if (i < Q4 + 2 * K4 + W4) {
        int jj = i - (Q4 + 2 * K4);
        int widx = jj >> 16;
        j = jj & 65535;
        src = (widx == 0) ? w0 : (widx == 1) ? w1 : (widx == 2) ? w2 : w3;
        hi = wh + (size_t)widx * HH * HH;
        lo = wl + (size_t)widx * HH * HH;
    } else {
        int jj = i - (Q4 + 2 * K4 + W4);
        int base = jj * 4;
#pragma unroll
        for (int e = 0; e < 4; e++) {
            int idx = base + e;
            int d = idx >> 10, l = idx & 1023;
            float v = pe[idx];
            __nv_bfloat16 h = __float2bfloat16(v);
            peh[l * 64 + d] = h;
            pel[l * 64 + d] = __float2bfloat16(v - __bfloat162float(h));
        }
        return;
    }

    float4 v = ((const float4*)src)[j];
    __nv_bfloat16 h0 = __float2bfloat16(v.x), h1 = __float2bfloat16(v.y);
    __nv_bfloat16 h2 = __float2bfloat16(v.z), h3 = __float2bfloat16(v.w);
    ((__nv_bfloat162*)hi)[2 * j]     = __nv_bfloat162(h0, h1);
    ((__nv_bfloat162*)hi)[2 * j + 1] = __nv_bfloat162(h2, h3);
    ((__nv_bfloat162*)lo)[2 * j] = __nv_bfloat162(
        __float2bfloat16(v.x - __bfloat162float(h0)),
        __float2bfloat16(v.y - __bfloat162float(h1)));
    ((__nv_bfloat162*)lo)[2 * j + 1] = __nv_bfloat162(
        __float2bfloat16(v.z - __bfloat162float(h2)),
        __float2bfloat16(v.w - __bfloat162float(h3)));
}

// ---------------------------------------------------------------------------
// FUSED Q/K/V projection (R12 winner).
// ---------------------------------------------------------------------------
#define GSTG 36864
#define GEMM_DYN (3 * GSTG)

__global__ void __launch_bounds__(256) gemm_qkv(
    const __nv_bfloat16* __restrict__ iqh, const __nv_bfloat16* __restrict__ iql,
    const __nv_bfloat16* __restrict__ ikh, const __nv_bfloat16* __restrict__ ikl,
    const __nv_bfloat16* __restrict__ ivh, const __nv_bfloat16* __restrict__ ivl,
    const __nv_bfloat16* __restrict__ wh, const __nv_bfloat16* __restrict__ wl,
    __nv_bfloat16* __restrict__ hqh, __nv_bfloat16* __restrict__ hql,
    __nv_bfloat16* __restrict__ hkh, __nv_bfloat16* __restrict__ hkl,
    __nv_bfloat16* __restrict__ hvh, __nv_bfloat16* __restrict__ hvl) {
    extern __shared__ __align__(128) char dynsm[];
    const int t = threadIdx.x;
    const int wid = t >> 5, lane = t & 31;
    const int wm = wid & 3, wn = wid >> 2;
    const uint32_t sbase = smem_u32(dynsm);

    const int x = blockIdx.x;
    const __nv_bfloat16 *Ah, *Al, *Wh_, *Wl_;
    __nv_bfloat16 *Chi, *Clo;
    int rb, T;
    float scale;
    if (x < 32) {
        Ah = iqh; Al = iql;
        Wh_ = wh; Wl_ = wl;
        Chi = hqh; Clo = hql;
        rb = x * 128; T = MM; scale = 0.125f;
    } else if (x < 128) {
        Ah = ikh; Al = ikl;
        Wh_ = wh + (size_t)HH * HH; Wl_ = wl + (size_t)HH * HH;
        Chi = hkh; Clo = hkl;
        rb = (x - 32) * 128; T = NN; scale = 1.0f;
    } else {
        Ah = ivh; Al = ivl;
        Wh_ = wh + 2 * (size_t)HH * HH; Wl_ = wl + 2 * (size_t)HH * HH;
        Chi = hvh; Clo = hvl;
        rb = (x - 128) * 128; T = NN; scale = 1.0f;
    }
    const int jb = blockIdx.y * 128;

    const uint32_t a_off = (uint32_t)((wm * 32 + (lane & 15)) * 144 + (lane >> 4) * 16);
    const uint32_t b_off = (uint32_t)((wn * 64 + (lane & 7) + ((lane >> 4) & 1) * 8) * 144
                                      + ((lane >> 3) & 1) * 16);

    float acc[2][8][4];
#pragma unroll
    for (int i = 0; i < 2; i++)
#pragma unroll
        for (int j = 0; j < 8; j++)
#pragma unroll
            for (int e = 0; e < 4; e++) acc[i][j][e] = 0.f;

    auto issue_stage = [&](int s, int ch) {
        const int term = ch >> 3, kc = ch & 7;
        const __nv_bfloat16* As = (term == 2) ? Al : Ah;
        const __nv_bfloat16* Ws = (term == 1) ? Wl_ : Wh_;
        const __nv_bfloat16* Ag = As + (size_t)rb * HH + kc * 64;
        const __nv_bfloat16* Wg = Ws + (size_t)jb * HH + kc * 64;
        const uint32_t sA = sbase + s * GSTG;
        const uint32_t sB = sA + 18432;
#pragma unroll
        for (int e = 0; e < 4; e++) {
            int id = t + e * 256, row = id >> 3, seg = id & 7;
            uint32_t dst = row * 144 + seg * 16;
            size_t so = (size_t)row * HH + seg * 8;
            CPA16(sA + dst, Ag + so);
            CPA16(sB + dst, Wg + so);
        }
    };

    issue_stage(0, 0);
    CP_COMMIT();
    issue_stage(1, 1);
    CP_COMMIT();

    for (int ch = 0; ch < 24; ch++) {
        if (ch < 23) CP_WAIT1(); else CP_WAIT0();
        __syncthreads();
        if (ch + 2 < 24) {
            issue_stage((ch + 2) % 3, ch + 2);
            CP_COMMIT();
        }

        const uint32_t sA = sbase + (ch % 3) * GSTG;
        const uint32_t sB = sA + 18432;
#pragma unroll
        for (int ks = 0; ks < 4; ks++) {
            uint32_t a[2][4], b[8][2];
#pragma unroll
            for (int mi = 0; mi < 2; mi++)
                ldsm4(a[mi], sA + a_off + mi * 16 * 144 + ks * 32);
#pragma unroll
            for (int j = 0; j < 4; j++) {
                uint32_t r4[4];
                ldsm4(r4, sB + b_off + j * 16 * 144 + ks * 32);
                b[2 * j][0] = r4[0]; b[2 * j][1] = r4[1];
                b[2 * j + 1][0] = r4[2]; b[2 * j + 1][1] = r4[3];
            }
#pragma unroll
            for (int mi = 0; mi < 2; mi++)
#pragma unroll
                for (int nj = 0; nj < 8; nj++)
                    mma16816(acc[mi][nj], a[mi], b[nj]);
        }
    }

    const int g = lane >> 2, t4 = lane & 3;
#pragma unroll
    for (int mi = 0; mi < 2; mi++) {
        const int r0 = rb + wm * 32 + mi * 16 + g;
#pragma unroll
        for (int nj = 0; nj < 8; nj++) {
            const int jcol = jb + wn * 64 + nj * 8 + t4 * 2;
            float v0 = acc[mi][nj][0] * scale, v1 = acc[mi][nj][1] * scale;
            float v2 = acc[mi][nj][2] * scale, v3 = acc[mi][nj][3] * scale;
            const int head = (jcol >> 6) & 7, dd = jcol & 63;
            int b0 = r0 / T, tt0 = r0 % T;
            int b1 = (r0 + 8) / T, tt1 = (r0 + 8) % T;
            size_t o0 = (((size_t)(b0 * 8 + head) * T + tt0) << 6) + dd;
            size_t o1 = (((size_t)(b1 * 8 + head) * T + tt1) << 6) + dd;
            *(uint32_t*)(Chi + o0) = packbf(v0, v1);
            *(uint32_t*)(Chi + o1) = packbf(v2, v3);
            *(uint32_t*)(Clo + o0) = packbf_lo(v0, v1);
            *(uint32_t*)(Clo + o1) = packbf_lo(v2, v3);
        }
    }
}

// ---------------------------------------------------------------------------
// Output projection GEMM (fp32 out).
// ---------------------------------------------------------------------------
__global__ void __launch_bounds__(256) gemm_out(const __nv_bfloat16* __restrict__ Ah,
                                                const __nv_bfloat16* __restrict__ Al,
                                                const __nv_bfloat16* __restrict__ Wh,
                                                const __nv_bfloat16* __restrict__ Wl,
                                                float* __restrict__ C) {
    extern __shared__ __align__(128) char dynsm[];
    const int t = threadIdx.x;
    const int wid = t >> 5, lane = t & 31;
    const int wm = wid & 3, wn = wid >> 2;
    const int rb = blockIdx.x * 128, jb = blockIdx.y * 128;
    const uint32_t sbase = smem_u32(dynsm);

    const uint32_t a_off = (uint32_t)((wm * 32 + (lane & 15)) * 144 + (lane >> 4) * 16);
    const uint32_t b_off = (uint32_t)((wn * 64 + (lane & 7) + ((lane >> 4) & 1) * 8) * 144
                                      + ((lane >> 3) & 1) * 16);

    float acc[2][8][4];
#pragma unroll
    for (int i = 0; i < 2; i++)
#pragma unroll
        for (int j = 0; j < 8; j++)
#pragma unroll
            for (int e = 0; e < 4; e++) acc[i][j][e] = 0.f;

    auto issue_stage = [&](int s, int ch) {
        const int term = ch >> 3, kc = ch & 7;
        const __nv_bfloat16* As = (term == 2) ? Al : Ah;
        const __nv_bfloat16* Ws = (term == 1) ? Wl : Wh;
        const __nv_bfloat16* Ag = As + (size_t)rb * HH + kc * 64;
        const __nv_bfloat16* Wg = Ws + (size_t)jb * HH + kc * 64;
        const uint32_t sA = sbase + s * GSTG;
        const uint32_t sB = sA + 18432;
#pragma unroll
        for (int e = 0; e < 4; e++) {
            int id = t + e * 256, row = id >> 3, seg = id & 7;
            uint32_t dst = row * 144 + seg * 16;
            size_t so = (size_t)row * HH + seg * 8;
            CPA16(sA + dst, Ag + so);
            CPA16(sB + dst, Wg + so);
        }
    };

    issue_stage(0, 0);
    CP_COMMIT();
    issue_stage(1, 1);
    CP_COMMIT();

    for (int ch = 0; ch < 24; ch++) {
        if (ch < 23) CP_WAIT1(); else CP_WAIT0();
        __syncthreads();
        if (ch + 2 < 24) {
            issue_stage((ch + 2) % 3, ch + 2);
            CP_COMMIT();
        }

        const uint32_t sA = sbase + (ch % 3) * GSTG;
        const uint32_t sB = sA + 18432;
#pragma unroll
        for (int ks = 0; ks < 4; ks++) {
            uint32_t a[2][4], b[8][2];
#pragma unroll
            for (int mi = 0; mi < 2; mi++)
                ldsm4(a[mi], sA + a_off + mi * 16 * 144 + ks * 32);
#pragma unroll
            for (int j = 0; j < 4; j++) {
                uint32_t r4[4];
                ldsm4(r4, sB + b_off + j * 16 * 144 + ks * 32);
                b[2 * j][0] = r4[0]; b[2 * j][1] = r4[1];
                b[2 * j + 1][0] = r4[2]; b[2 * j + 1][1] = r4[3];
            }
#pragma unroll
            for (int mi = 0; mi < 2; mi++)
#pragma unroll
                for (int nj = 0; nj < 8; nj++)
                    mma16816(acc[mi][nj], a[mi], b[nj]);
        }
    }

    const int g = lane >> 2, t4 = lane & 3;
#pragma unroll
    for (int mi = 0; mi < 2; mi++) {
        const int r0 = rb + wm * 32 + mi * 16 + g;
#pragma unroll
        for (int nj = 0; nj < 8; nj++) {
            const int jcol = jb + wn * 64 + nj * 8 + t4 * 2;
            *(float2*)(C + (size_t)r0 * HH + jcol) =
                make_float2(acc[mi][nj][0], acc[mi][nj][1]);
            *(float2*)(C + (size_t)(r0 + 8) * HH + jcol) =
                make_float2(acc[mi][nj][2], acc[mi][nj][3]);
        }
    }
}

// ---------------------------------------------------------------------------
// HMMA flash banded attention with FUSED positional GEMM.
// R12 base (128 thr, 88KB smem, 2 CTAs/SM). Per chunk:
//   stage K/V hi/lo + pe_t slice hi/lo (rows 64c..64c+63, L2-hot),
//   Spos slice = 3-term MMA (qhat . pe_t) -> written to sSpf ring (fp32),
//   then S = QK-MMA + ring add, softmax, PV as before.
// Q prologue overlays the pe staging region.
// ---------------------------------------------------------------------------
#define SKH 0
#define SKL 9216
#define SVH 18432
#define SVL 27648
#define SPEH 36864
#define SPEL 46080
#define SSP 55296
#define ATTN_SMEM (SSP + 64 * 128 * 4)   // 88064

__global__ void __launch_bounds__(128) attn3(
    const __nv_bfloat16* __restrict__ qhh, const __nv_bfloat16* __restrict__ qhl,
    const __nv_bfloat16* __restrict__ khh, const __nv_bfloat16* __restrict__ khl,
    const __nv_bfloat16* __restrict__ vhh, const __nv_bfloat16* __restrict__ vhl,
    const __nv_bfloat16* __restrict__ peh, const __nv_bfloat16* __restrict__ pel,
    __nv_bfloat16* __restrict__ aoh, __nv_bfloat16* __restrict__ aol) {
    extern __shared__ __align__(16) char smc[];
    const uint32_t sb = smem_u32(smc);
    float* sSpf = (float*)(smc + SSP);

    const int m0 = blockIdx.x * 64;
    const int bh = blockIdx.y;
    const int t = threadIdx.x, lane = t & 31, wm = t >> 5;
    const int g = lane >> 2, t4 = lane & 3;
    const int i0 = wm * 16 + g;

    // ---- prologue: stage Q into the pe region, extract frags ----
#pragma unroll
    for (int e = 0; e < 4; e++) {
        int id = t + e * 128, row = id >> 3, seg = id & 7;
        size_t srow = ((size_t)bh * MM + m0 + row) * 64 + seg * 8;
        uint32_t dst = row * 144 + seg * 16;
        *(uint4*)(smc + SPEH + dst) = *(const uint4*)(qhh + srow);
        *(uint4*)(smc + SPEL + dst) = *(const uint4*)(qhl + srow);
    }
    __syncthreads();

    uint32_t qa_h[4][4], qa_l[4][4];
    {
        const uint32_t arel = (wm * 16 + (lane & 15)) * 144 + (lane >> 4) * 16;
#pragma unroll
        for (int ks = 0; ks < 4; ks++) {
            ldsm4(qa_h[ks], sb + SPEH + arel + ks * 32);
            ldsm4(qa_l[ks], sb + SPEL + arel + ks * 32);
        }
    }
    // chunk loop's leading sync orders extraction before pe staging overwrite

    const uint32_t bKrel = ((lane & 7) + ((lane >> 4) & 1) * 8) * 144
                         + ((lane >> 3) & 1) * 16;
    const uint32_t bVrel = (lane & 15) * 144 + (lane >> 4) * 16;

    float o[8][4];
#pragma unroll
    for (int j = 0; j < 8; j++)
#pragma unroll
        for (int e = 0; e < 4; e++) o[j][e] = 0.f;
    float rmax0 = -1e30f, rmax1 = -1e30f, rsum0 = 0.f, rsum1 = 0.f;

    for (int c = 0; c < 17; c++) {
        __syncthreads();
        // ---- stage K, V hi/lo + pe_t slice hi/lo ----
        {
            const size_t nbase = (size_t)bh * NN + m0 + c * 64;
            const int gbase = c * 64;
#pragma unroll
            for (int e = 0; e < 4; e++) {
                int id = t + e * 128, row = id >> 3, seg = id & 7;
                size_t srow = (nbase + row) * 64 + seg * 8;
                uint32_t dst = row * 144 + seg * 16;
                *(uint4*)(smc + SKH + dst) = *(const uint4*)(khh + srow);
                *(uint4*)(smc + SKL + dst) = *(const uint4*)(khl + srow);
                *(uint4*)(smc + SVH + dst) = *(const uint4*)(vhh + srow);
                *(uint4*)(smc + SVL + dst) = *(const uint4*)(vhl + srow);
                if (gbase + row < LL) {
                    size_t prow = (size_t)(gbase + row) * 64 + seg * 8;
                    *(uint4*)(smc + SPEH + dst) = *(const uint4*)(peh + prow);
                    *(uint4*)(smc + SPEL + dst) = *(const uint4*)(pel + prow);
                } else {
                    *(uint4*)(smc + SPEH + dst) = make_uint4(0, 0, 0, 0);
                    *(uint4*)(smc + SPEL + dst) = make_uint4(0, 0, 0, 0);
                }
            }
        }
        __syncthreads();

        const int destbase = 64 * (c & 1);

        // ---- Spos slice = qhat . pe_t (3-term MMA) -> ring ----
        {
            float s2[8][4];
#pragma unroll
            for (int j = 0; j < 8; j++)
#pragma unroll
                for (int e = 0; e < 4; e++) s2[j][e] = 0.f;
#pragma unroll
            for (int ks = 0; ks < 4; ks++) {
#pragma unroll
                for (int nb = 0; nb < 4; nb++) {
                    uint32_t rh[4], rl[4];
                    ldsm4(rh, sb + SPEH + bKrel + nb * 16 * 144 + ks * 32);
                    ldsm4(rl, sb + SPEL + bKrel + nb * 16 * 144 + ks * 32);
                    mma16816(s2[2 * nb],     qa_h[ks], rh);
                    mma16816(s2[2 * nb + 1], qa_h[ks], rh + 2);
                    mma16816(s2[2 * nb],     qa_l[ks], rh);
                    mma16816(s2[2 * nb + 1], qa_l[ks], rh + 2);
                    mma16816(s2[2 * nb],     qa_h[ks], rl);
                    mma16816(s2[2 * nb + 1], qa_h[ks], rl + 2);
                }
            }
            // write 64 new ring cols (rows i0, i0+8 are warp-private)
#pragma unroll
            for (int nj = 0; nj < 8; nj++) {
                int jn = destbase + nj * 8 + t4 * 2;
                sSpf[i0 * 128 + jn] = s2[nj][0];
                sSpf[i0 * 128 + jn + 1] = s2[nj][1];
                sSpf[(i0 + 8) * 128 + jn] = s2[nj][2];
                sSpf[(i0 + 8) * 128 + jn + 1] = s2[nj][3];
            }
            __syncwarp();
        }

        // ---- S = qhat . k (3-term) ----
        float s[8][4];
#pragma unroll
        for (int j = 0; j < 8; j++)
#pragma unroll
            for (int e = 0; e < 4; e++) s[j][e] = 0.f;
#pragma unroll
        for (int ks = 0; ks < 4; ks++) {
#pragma unroll
            for (int nb = 0; nb < 4; nb++) {
                uint32_t rh[4], rl[4];
                ldsm4(rh, sb + SKH + bKrel + nb * 16 * 144 + ks * 32);
                ldsm4(rl, sb + SKL + bKrel + nb * 16 * 144 + ks * 32);
                mma16816(s[2 * nb],     qa_h[ks], rh);
                mma16816(s[2 * nb + 1], qa_h[ks], rh + 2);
                mma16816(s[2 * nb],     qa_l[ks], rh);
                mma16816(s[2 * nb + 1], qa_l[ks], rh + 2);
                mma16816(s[2 * nb],     qa_h[ks], rl);
                mma16816(s[2 * nb + 1], qa_h[ks], rl + 2);
            }
        }

        // ---- add Spos via ring index; stale entries masked below ----
#pragma unroll
        for (int nj = 0; nj < 8; nj++) {
            int base = 64 * c + nj * 8 + t4 * 2 - i0 + 128;
            s[nj][0] += sSpf[i0 * 128 + (base & 127)];
            s[nj][1] += sSpf[i0 * 128 + ((base + 1) & 127)];
            s[nj][2] += sSpf[(i0 + 8) * 128 + ((base - 8) & 127)];
            s[nj][3] += sSpf[(i0 + 8) * 128 + ((base - 7) & 127)];
        }
        if (c == 0) {
#pragma unroll
            for (int nj = 0; nj < 8; nj++) {
                int j0 = nj * 8 + t4 * 2;
                if (j0 < i0) s[nj][0] = -1e30f;
                if (j0 + 1 < i0) s[nj][1] = -1e30f;
                if (j0 < i0 + 8) s[nj][2] = -1e30f;
                if (j0 + 1 < i0 + 8) s[nj][3] = -1e30f;
            }
        } else if (c == 16) {
#pragma unroll
            for (int nj = 0; nj < 8; nj++) {
                int j0 = nj * 8 + t4 * 2;
                if (j0 >= i0) s[nj][0] = -1e30f;
                if (j0 + 1 >= i0) s[nj][1] = -1e30f;
                if (j0 >= i0 + 8) s[nj][2] = -1e30f;
                if (j0 + 1 >= i0 + 8) s[nj][3] = -1e30f;
            }
        }

        // ---- online softmax ----
        {
            float mx0 = -1e30f, mx1 = -1e30f;
#pragma unroll
            for (int nj = 0; nj < 8; nj++) {
                mx0 = fmaxf(mx0, fmaxf(s[nj][0], s[nj][1]));
                mx1 = fmaxf(mx1, fmaxf(s[nj][2], s[nj][3]));
            }
            mx0 = fmaxf(mx0, __shfl_xor_sync(0xffffffffu, mx0, 1));
            mx0 = fmaxf(mx0, __shfl_xor_sync(0xffffffffu, mx0, 2));
            mx1 = fmaxf(mx1, __shfl_xor_sync(0xffffffffu, mx1, 1));
            mx1 = fmaxf(mx1, __shfl_xor_sync(0xffffffffu, mx1, 2));
            float nm0 = fmaxf(rmax0, mx0), nm1 = fmaxf(rmax1, mx1);
            float corr0 = __expf(rmax0 - nm0), corr1 = __expf(rmax1 - nm1);
            rmax0 = nm0; rmax1 = nm1;
            float ls0 = 0.f, ls1 = 0.f;
#pragma unroll
            for (int nj = 0; nj < 8; nj++) {
                s[nj][0] = __expf(s[nj][0] - nm0);
                s[nj][1] = __expf(s[nj][1] - nm0);
                s[nj][2] = __expf(s[nj][2] - nm1);
                s[nj][3] = __expf(s[nj][3] - nm1);
                ls0 += s[nj][0] + s[nj][1];
                ls1 += s[nj][2] + s[nj][3];
            }
            ls0 += __shfl_xor_sync(0xffffffffu, ls0, 1);
            ls0 += __shfl_xor_sync(0xffffffffu, ls0, 2);
            ls1 += __shfl_xor_sync(0xffffffffu, ls1, 1);
            ls1 += __shfl_xor_sync(0xffffffffu, ls1, 2);
            rsum0 = rsum0 * corr0 + ls0;
            rsum1 = rsum1 * corr1 + ls1;
#pragma unroll
            for (int j = 0; j < 8; j++) {
                o[j][0] *= corr0; o[j][1] *= corr0;
                o[j][2] *= corr1; o[j][3] *= corr1;
            }
        }

        // ---- O += P . V (3-term, P split in registers) ----
#pragma unroll
        for (int ks = 0; ks < 4; ks++) {
            uint32_t pah[4], pal[4];
            pah[0] = packbf(s[2 * ks][0], s[2 * ks][1]);
            pah[1] = packbf(s[2 * ks][2], s[2 * ks][3]);
            pah[2] = packbf(s[2 * ks + 1][0], s[2 * ks + 1][1]);
            pah[3] = packbf(s[2 * ks + 1][2], s[2 * ks + 1][3]);
            pal[0] = packbf_lo(s[2 * ks][0], s[2 * ks][1]);
            pal[1] = packbf_lo(s[2 * ks][2], s[2 * ks][3]);
            pal[2] = packbf_lo(s[2 * ks + 1][0], s[2 * ks + 1][1]);
            pal[3] = packbf_lo(s[2 * ks + 1][2], s[2 * ks + 1][3]);
#pragma unroll
            for (int dj = 0; dj < 4; dj++) {
                uint32_t rh[4], rl[4];
                ldsm4t(rh, sb + SVH + bVrel + ks * 16 * 144 + dj * 32);
                ldsm4t(rl, sb + SVL + bVrel + ks * 16 * 144 + dj * 32);
                mma16816(o[2 * dj],     pah, rh);
                mma16816(o[2 * dj + 1], pah, rh + 2);
                mma16816(o[2 * dj],     pal, rh);
                mma16816(o[2 * dj + 1], pal, rh + 2);
                mma16816(o[2 * dj],     pah, rl);
                mma16816(o[2 * dj + 1], pah, rl + 2);
            }
        }
    }

    // ---- epilogue ----
    {
        float inv0 = 1.f / rsum0, inv1 = 1.f / rsum1;
        int b = bh >> 3, hd = bh & 7;
        int mr = m0 + i0;
#pragma unroll
        for (int nj = 0; nj < 8; nj++) {
            int col = hd * 64 + nj * 8 + t4 * 2;
            size_t idx0 = ((size_t)(b * MM + mr) * HH) + col;
            size_t idx1 = ((size_t)(b * MM + mr + 8) * HH) + col;
            float a0 = o[nj][0] * inv0, a1 = o[nj][1] * inv0;
            float a2 = o[nj][2] * inv1, a3 = o[nj][3] * inv1;
            *(uint32_t*)(aoh + idx0) = packbf(a0, a1);
            *(uint32_t*)(aoh + idx1) = packbf(a2, a3);
            *(uint32_t*)(aol + idx0) = packbf_lo(a0, a1);
            *(uint32_t*)(aol + idx1) = packbf_lo(a2, a3);
        }
    }
}

// ---------------------------------------------------------------------------
extern "C" void kernel_launch(void* const* d_in, const int* in_sizes, int n_in,
                              void* d_out, int out_size) {
    const float* query  = (const float*)d_in[0];
    const float* key    = (const float*)d_in[1];
    const float* value  = (const float*)d_in[2];
    const float* key_pe = (const float*)d_in[3];
    const float* Wq     = (const float*)d_in[4];
    const float* Wk     = (const float*)d_in[5];
    const float* Wv     = (const float*)d_in[6];
    const float* Wo     = (const float*)d_in[7];
    float* out = (float*)d_out;

    __nv_bfloat16 *iqh, *iql, *ikh, *ikl, *ivh, *ivl;
    __nv_bfloat16 *hqh, *hql, *hkh, *hkl, *hvh, *hvl;
    __nv_bfloat16 *aoh, *aol, *wh, *wl, *peh, *pel;
    cudaGetSymbolAddress((void**)&iqh, g_iqh); cudaGetSymbolAddress((void**)&iql, g_iql);
    cudaGetSymbolAddress((void**)&ikh, g_ikh); cudaGetSymbolAddress((void**)&ikl, g_ikl);
    cudaGetSymbolAddress((void**)&ivh, g_ivh); cudaGetSymbolAddress((void**)&ivl, g_ivl);
    cudaGetSymbolAddress((void**)&hqh, g_hqh); cudaGetSymbolAddress((void**)&hql, g_hql);
    cudaGetSymbolAddress((void**)&hkh, g_hkh); cudaGetSymbolAddress((void**)&hkl, g_hkl);
    cudaGetSymbolAddress((void**)&hvh, g_hvh); cudaGetSymbolAddress((void**)&hvl, g_hvl);
    cudaGetSymbolAddress((void**)&aoh, g_aoh); cudaGetSymbolAddress((void**)&aol, g_aol);
    cudaGetSymbolAddress((void**)&wh, g_wh);   cudaGetSymbolAddress((void**)&wl, g_wl);
    cudaGetSymbolAddress((void**)&peh, g_peh); cudaGetSymbolAddress((void**)&pel, g_pel);

    static bool attr_set = false;
    if (!attr_set) {
        cudaFuncSetAttribute(attn3, cudaFuncAttributeMaxDynamicSharedMemorySize,
                             ATTN_SMEM);
        cudaFuncSetAttribute(gemm_qkv, cudaFuncAttributeMaxDynamicSharedMemorySize,
                             GEMM_DYN);
        cudaFuncSetAttribute(gemm_out, cudaFuncAttributeMaxDynamicSharedMemorySize,
                             GEMM_DYN);
        attr_set = true;
    }

    // fused splits (one launch)
    split_all<<<(TOT4 + 255) / 256, 256>>>(query, key, value, Wq, Wk, Wv, Wo,
                                           key_pe, iqh, iql, ikh, ikl, ivh, ivl,
                                           wh, wl, peh, pel);

    // FUSED Q+K+V projections
    gemm_qkv<<<dim3(224, 4), 256, GEMM_DYN>>>(iqh, iql, ikh, ikl, ivh, ivl,
                                              wh, wl, hqh, hql, hkh, hkl,
                                              hvh, hvl);

    // flash banded attention (positional GEMM fused in)
    attn3<<<dim3(MM / 64, 64), 128, ATTN_SMEM>>>(hqh, hql, hkh, hkl, hvh, hvl,
                                                 peh, pel, aoh, aol);

    // output projection (fp32 out)
    gemm_out<<<dim3(BB * MM / 128, 4), 256, GEMM_DYN>>>(
        aoh, aol, wh + 3 * (size_t)HH * HH, wl + 3 * (size_t)HH * HH, out);
}